// round 2
// baseline (speedup 1.0000x reference)
#include <cuda_runtime.h>
#include <math.h>

#define B_  8
#define S_  1024
#define H_  512
#define NH_ 8
#define HD_ 64

// Scratch (device globals: allocation-free). Values stored already tf32-quantized.
__device__ float g_q[B_*NH_*S_*HD_];   // [B,NH,S,HD], pre-scaled by 1/sqrt(HD)
__device__ float g_k[B_*NH_*S_*HD_];   // [B,NH,S,HD]
__device__ float g_v[B_*NH_*S_*HD_];   // [B,NH,S,HD] (row-major, no transpose)

__device__ __forceinline__ float to_tf32(float x) {
    unsigned u;
    asm("cvt.rna.tf32.f32 %0, %1;" : "=r"(u) : "f"(x));
    return __uint_as_float(u);
}

__device__ __forceinline__ void mma8(float c[4], const float a[4], float b0, float b1) {
    asm volatile(
        "mma.sync.aligned.m16n8k8.row.col.f32.tf32.tf32.f32 "
        "{%0,%1,%2,%3}, {%4,%5,%6,%7}, {%8,%9}, {%0,%1,%2,%3};\n"
        : "+f"(c[0]), "+f"(c[1]), "+f"(c[2]), "+f"(c[3])
        : "r"(__float_as_uint(a[0])), "r"(__float_as_uint(a[1])),
          "r"(__float_as_uint(a[2])), "r"(__float_as_uint(a[3])),
          "r"(__float_as_uint(b0)), "r"(__float_as_uint(b1)));
}

// ---------------------------------------------------------------------------
// Projection: out[m,n] = sum_k X[m,k] * W[n,k] + bias[n]
// grid: (M/128, N/64, 3)  block: 256.  Pair-packed SMEM: slot (r, kk*4+j)
// holds (T[r][kk*8+j], T[r][kk*8+j+4]) as float2.  Row stride 20 f2.
// ---------------------------------------------------------------------------
__global__ __launch_bounds__(256) void proj_kernel(
    const float* __restrict__ X,
    const float* __restrict__ Wq, const float* __restrict__ bq,
    const float* __restrict__ Wk, const float* __restrict__ bk,
    const float* __restrict__ Wv, const float* __restrict__ bv)
{
    __shared__ float2 Xp[128 * 20];
    __shared__ float2 Wp[64 * 20];

    const int zw = blockIdx.z;
    const float* W  = (zw == 0) ? Wq : (zw == 1) ? Wk : Wv;
    const float* bb = (zw == 0) ? bq : (zw == 1) ? bk : bv;
    float* dstbase  = (zw == 0) ? g_q : (zw == 1) ? g_k : g_v;
    const float osc = (zw == 0) ? 0.125f : 1.0f;

    const int m0 = blockIdx.x * 128;
    const int n0 = blockIdx.y * 64;
    const int tid  = threadIdx.x;
    const int lane = tid & 31;
    const int wid  = tid >> 5;
    const int wm = (wid & 3) * 32;
    const int wn = (wid >> 2) * 32;
    const int g = lane >> 2;
    const int t = lane & 3;

    float acc[2][4][4];
#pragma unroll
    for (int i = 0; i < 2; i++)
#pragma unroll
        for (int j = 0; j < 4; j++)
#pragma unroll
            for (int r = 0; r < 4; r++) acc[i][j][r] = 0.f;

    for (int kc = 0; kc < 512; kc += 32) {
        // Stage X tile 128x32 into pair layout (512 tasks)
#pragma unroll
        for (int p = 0; p < 2; p++) {
            int idx = tid + p * 256;
            int r = idx >> 2, kk = idx & 3;
            const float* src = &X[(m0 + r) * 512 + kc + kk * 8];
            float4 va = *(const float4*)src;
            float4 vb = *(const float4*)(src + 4);
            float4 w0 = make_float4(to_tf32(va.x), to_tf32(vb.x), to_tf32(va.y), to_tf32(vb.y));
            float4 w1 = make_float4(to_tf32(va.z), to_tf32(vb.z), to_tf32(va.w), to_tf32(vb.w));
            *(float4*)&Xp[r * 20 + kk * 4]     = w0;
            *(float4*)&Xp[r * 20 + kk * 4 + 2] = w1;
        }
        // Stage W tile 64x32 (256 tasks)
        {
            int r = tid >> 2, kk = tid & 3;
            const float* src = &W[(n0 + r) * 512 + kc + kk * 8];
            float4 va = *(const float4*)src;
            float4 vb = *(const float4*)(src + 4);
            float4 w0 = make_float4(to_tf32(va.x), to_tf32(vb.x), to_tf32(va.y), to_tf32(vb.y));
            float4 w1 = make_float4(to_tf32(va.z), to_tf32(vb.z), to_tf32(va.w), to_tf32(vb.w));
            *(float4*)&Wp[r * 20 + kk * 4]     = w0;
            *(float4*)&Wp[r * 20 + kk * 4 + 2] = w1;
        }
        __syncthreads();

#pragma unroll
        for (int kk = 0; kk < 4; kk++) {
            float a[2][4];
#pragma unroll
            for (int i = 0; i < 2; i++) {
                int r = wm + i * 16 + g;
                float2 lo = Xp[r * 20 + kk * 4 + t];
                float2 hi = Xp[(r + 8) * 20 + kk * 4 + t];
                a[i][0] = lo.x; a[i][1] = hi.x; a[i][2] = lo.y; a[i][3] = hi.y;
            }
#pragma unroll
            for (int j = 0; j < 4; j++) {
                float2 b2 = Wp[(wn + j * 8 + g) * 20 + kk * 4 + t];
#pragma unroll
                for (int i = 0; i < 2; i++) mma8(acc[i][j], a[i], b2.x, b2.y);
            }
        }
        __syncthreads();
    }

    // Epilogue: bias + tf32 quantize + coalesced-ish float2 stores, row-major
#pragma unroll
    for (int i = 0; i < 2; i++) {
#pragma unroll
        for (int j = 0; j < 4; j++) {
            int n = n0 + wn + j * 8 + t * 2;
            float b0 = bb[n], b1 = bb[n + 1];
            int h = n >> 6, d = n & 63;
#pragma unroll
            for (int rr = 0; rr < 2; rr++) {
                int m = m0 + wm + i * 16 + g + rr * 8;
                int bI = m >> 10, s = m & 1023;
                float2 v;
                v.x = to_tf32((acc[i][j][rr * 2 + 0] + b0) * osc);
                v.y = to_tf32((acc[i][j][rr * 2 + 1] + b1) * osc);
                *(float2*)&dstbase[(((bI * NH_ + h) * S_) + s) * HD_ + d] = v;
            }
        }
    }
}

// ---------------------------------------------------------------------------
// Flash attention with rel bias + additive mask.
// grid: (S/128, NH, B)  block: 256 (8 warps x 16 q-rows), k-block 32.
// ---------------------------------------------------------------------------
__global__ __launch_bounds__(256) void attn_kernel(
    const float* __restrict__ rel,   // [B,NH,S,S]
    const float* __restrict__ mask,  // [B,1,1,S]
    float* __restrict__ out)         // [B,S,H]
{
    // K pair layout: Kp[r][kk*4+j] = (K[r][kk*8+j], K[r][kk*8+j+4]); stride 36 f2
    __shared__ float2 Kp[32 * 36];
    // V row-pair layout (float view): Vsf[prow*136 + d*2 + sel],
    // slot (prow=kk*4+j, d) = (V[kk*8+j][d], V[kk*8+j+4][d])
    __shared__ float Vsf[16 * 136];
    // P pair layout (float view): Ps[r*40 + p*2 + sel]; stride 20 f2
    __shared__ float Ps[128 * 40];

    const int b = blockIdx.z, h = blockIdx.y;
    const int q0 = blockIdx.x * 128;
    const int tid  = threadIdx.x;
    const int lane = tid & 31;
    const int wid  = tid >> 5;
    const int wq = wid * 16;
    const int g = lane >> 2;
    const int t = lane & 3;

    // Q fragments resident in registers
    float qa[8][4];
    {
        const float* Qp = &g_q[(((size_t)(b * NH_ + h) * S_) + q0 + wq) * HD_];
#pragma unroll
        for (int kk = 0; kk < 8; kk++) {
            qa[kk][0] = Qp[(g    ) * 64 + kk * 8 + t];
            qa[kk][1] = Qp[(g + 8) * 64 + kk * 8 + t];
            qa[kk][2] = Qp[(g    ) * 64 + kk * 8 + t + 4];
            qa[kk][3] = Qp[(g + 8) * 64 + kk * 8 + t + 4];
        }
    }

    float o[8][4];
#pragma unroll
    for (int i = 0; i < 8; i++)
#pragma unroll
        for (int r = 0; r < 4; r++) o[i][r] = 0.f;

    float m0v = -INFINITY, m1v = -INFINITY;
    float l0 = 0.f, l1 = 0.f;

    const float* relbase = rel + ((size_t)((b * NH_ + h) * S_) + q0 + wq) * S_;
    const float* Kbase   = &g_k[((size_t)(b * NH_ + h) * S_) * 64];
    const float* Vbase   = &g_v[((size_t)(b * NH_ + h) * S_) * 64];
    const float* mbase   = mask + b * S_;

    for (int kb = 0; kb < S_; kb += 32) {
        // Stage K tile 32x64 in pair layout (256 tasks, 1/thread)
        {
            int r = tid >> 3, kk = tid & 7;
            const float* src = &Kbase[(kb + r) * 64 + kk * 8];
            float4 va = *(const float4*)src;
            float4 vb = *(const float4*)(src + 4);
            *(float4*)&Kp[r * 36 + kk * 4]     = make_float4(va.x, vb.x, va.y, vb.y);
            *(float4*)&Kp[r * 36 + kk * 4 + 2] = make_float4(va.z, vb.z, va.w, vb.w);
        }
        // Stage V tile 32x64 in row-pair layout (512 tasks)
#pragma unroll
        for (int p = 0; p < 2; p++) {
            int idx = tid + p * 256;
            int r = idx >> 4, c4 = (idx & 15) * 4;
            float4 v = *(const float4*)&Vbase[(kb + r) * 64 + c4];
            int kk = r >> 3, jj = r & 7;
            int prow = kk * 4 + (jj & 3);
            int sel  = jj >> 2;
            float* dst = &Vsf[prow * 136 + c4 * 2 + sel];
            dst[0] = v.x; dst[2] = v.y; dst[4] = v.z; dst[6] = v.w;
        }
        __syncthreads();

        // S = Q * K^T (16 x 32 per warp), B frags via LDS.64
        float s[4][4];
#pragma unroll
        for (int nf = 0; nf < 4; nf++)
#pragma unroll
            for (int r = 0; r < 4; r++) s[nf][r] = 0.f;
#pragma unroll
        for (int kk = 0; kk < 8; kk++) {
#pragma unroll
            for (int nf = 0; nf < 4; nf++) {
                float2 b2 = Kp[(nf * 8 + g) * 36 + kk * 4 + t];
                mma8(s[nf], qa[kk], b2.x, b2.y);
            }
        }

        // + rel bias + mask (float2 global loads)
#pragma unroll
        for (int nf = 0; nf < 4; nf++) {
            int col = kb + nf * 8 + t * 2;
            float2 mk = *(const float2*)&mbase[col];
            float2 r0 = *(const float2*)&relbase[(size_t)(g    ) * S_ + col];
            float2 r1 = *(const float2*)&relbase[(size_t)(g + 8) * S_ + col];
            s[nf][0] += r0.x + mk.x;  s[nf][1] += r0.y + mk.y;
            s[nf][2] += r1.x + mk.x;  s[nf][3] += r1.y + mk.y;
        }

        // Online softmax
        float tm0 = -INFINITY, tm1 = -INFINITY;
#pragma unroll
        for (int nf = 0; nf < 4; nf++) {
            tm0 = fmaxf(tm0, fmaxf(s[nf][0], s[nf][1]));
            tm1 = fmaxf(tm1, fmaxf(s[nf][2], s[nf][3]));
        }
        tm0 = fmaxf(tm0, __shfl_xor_sync(0xffffffffu, tm0, 1));
        tm0 = fmaxf(tm0, __shfl_xor_sync(0xffffffffu, tm0, 2));
        tm1 = fmaxf(tm1, __shfl_xor_sync(0xffffffffu, tm1, 1));
        tm1 = fmaxf(tm1, __shfl_xor_sync(0xffffffffu, tm1, 2));

        float mn0 = fmaxf(m0v, tm0), mn1 = fmaxf(m1v, tm1);
        float sc0 = __expf(m0v - mn0), sc1 = __expf(m1v - mn1);
        m0v = mn0; m1v = mn1;

        float rs0 = 0.f, rs1 = 0.f;
#pragma unroll
        for (int nf = 0; nf < 4; nf++) {
            s[nf][0] = __expf(s[nf][0] - mn0);
            s[nf][1] = __expf(s[nf][1] - mn0);
            s[nf][2] = __expf(s[nf][2] - mn1);
            s[nf][3] = __expf(s[nf][3] - mn1);
            rs0 += s[nf][0] + s[nf][1];
            rs1 += s[nf][2] + s[nf][3];
        }
        l0 = l0 * sc0 + rs0;
        l1 = l1 * sc1 + rs1;

#pragma unroll
        for (int nf = 0; nf < 8; nf++) {
            o[nf][0] *= sc0; o[nf][1] *= sc0;
            o[nf][2] *= sc1; o[nf][3] *= sc1;
        }

        // P -> SMEM pair layout (warp-local rows)
        {
            int sel = (t >= 2) ? 1 : 0;
            int jj  = (t & 1) * 2;   // pair slot within kk-group
#pragma unroll
            for (int nf = 0; nf < 4; nf++) {
                float* pr0 = &Ps[(wq + g    ) * 40 + (nf * 4 + jj) * 2 + sel];
                float* pr1 = &Ps[(wq + g + 8) * 40 + (nf * 4 + jj) * 2 + sel];
                pr0[0] = to_tf32(s[nf][0]);  pr0[2] = to_tf32(s[nf][1]);
                pr1[0] = to_tf32(s[nf][2]);  pr1[2] = to_tf32(s[nf][3]);
            }
        }
        __syncwarp();

        // O += P * V  (A via 2x LDS.64, B via 1x LDS.64)
#pragma unroll
        for (int kk = 0; kk < 4; kk++) {
            float2 lo = *(float2*)&Ps[(wq + g    ) * 40 + (kk * 4 + t) * 2];
            float2 hi = *(float2*)&Ps[(wq + g + 8) * 40 + (kk * 4 + t) * 2];
            float a[4] = {lo.x, hi.x, lo.y, hi.y};
#pragma unroll
            for (int nf = 0; nf < 8; nf++) {
                float2 vb = *(float2*)&Vsf[(kk * 4 + t) * 136 + (nf * 8 + g) * 2];
                mma8(o[nf], a, vb.x, vb.y);
            }
        }
        __syncthreads();
    }

    // Final normalization + store
    l0 += __shfl_xor_sync(0xffffffffu, l0, 1);
    l0 += __shfl_xor_sync(0xffffffffu, l0, 2);
    l1 += __shfl_xor_sync(0xffffffffu, l1, 1);
    l1 += __shfl_xor_sync(0xffffffffu, l1, 2);
    float inv0 = 1.f / l0, inv1 = 1.f / l1;

    int q = q0 + wq + g;
    float* ob0 = &out[((size_t)(b * S_ + q    )) * H_ + h * 64];
    float* ob1 = &out[((size_t)(b * S_ + q + 8)) * H_ + h * 64];
#pragma unroll
    for (int nf = 0; nf < 8; nf++) {
        int c = nf * 8 + t * 2;
        float2 v0 = make_float2(o[nf][0] * inv0, o[nf][1] * inv0);
        float2 v1 = make_float2(o[nf][2] * inv1, o[nf][3] * inv1);
        *(float2*)&ob0[c] = v0;
        *(float2*)&ob1[c] = v1;
    }
}

// ---------------------------------------------------------------------------
extern "C" void kernel_launch(void* const* d_in, const int* in_sizes, int n_in,
                              void* d_out, int out_size)
{
    const float* hidden = (const float*)d_in[0];
    const float* mask   = (const float*)d_in[1];
    const float* rel    = (const float*)d_in[2];
    const float* Wq     = (const float*)d_in[3];
    const float* bq     = (const float*)d_in[4];
    const float* Wk     = (const float*)d_in[5];
    const float* bk     = (const float*)d_in[6];
    const float* Wv     = (const float*)d_in[7];
    const float* bv     = (const float*)d_in[8];
    float* out = (float*)d_out;

    dim3 pg(64, 8, 3);
    proj_kernel<<<pg, 256>>>(hidden, Wq, bq, Wk, bk, Wv, bv);

    dim3 ag(8, NH_, B_);
    attn_kernel<<<ag, 256>>>(rel, mask, out);
}